// round 12
// baseline (speedup 1.0000x reference)
#include <cuda_runtime.h>
#include <cstdint>

#define NE       64
#define ND       1024
#define NTOK     65536
#define TILE_M   128
#define KC       16              // fp32 K per pipeline stage
#define NCHUNK   (ND / KC)       // 64
#define NTHREADS 256

// ---- static smem layout (float indices), padded-linear ----
// A stage: [2][KC][132]  (128 tokens + 4 pad)
// W stage: [2][KC][68]   (64 experts + 4 pad)
// epilogue overlay slog[128][64] = 8192 floats covers everything.
#define ROWA        132
#define ROWW        68
#define A_STAGEF    (KC * ROWA)            // 2112
#define W_BASE      (2 * A_STAGEF)         // 4224
#define W_STAGEF    (KC * ROWW)            // 1088
#define SMEM_FLOATS 8192                   // >= 4224 + 2176 = 6400

__device__ __forceinline__ void fma2(unsigned long long& acc,
                                     unsigned long long a,
                                     unsigned long long b) {
    asm("fma.rn.f32x2 %0, %1, %2, %0;" : "+l"(acc) : "l"(a), "l"(b));
}
__device__ __forceinline__ unsigned long long packdup(float f) {
    unsigned long long d;
    const uint32_t u = __float_as_uint(f);
    asm("mov.b64 %0, {%1, %1};" : "=l"(d) : "r"(u));
    return d;
}

__global__ __launch_bounds__(NTHREADS, 3)
void router_ffma2_kernel(const float* __restrict__ tokens,
                         const int* __restrict__ t_arr,
                         const float* __restrict__ Wg,
                         const float* __restrict__ bg,
                         float* __restrict__ out)
{
    __shared__ __align__(16) float smem[SMEM_FLOATS];

    const int tid = threadIdx.x;
    const int bm  = blockIdx.x * TILE_M;
    const int tg  = tid & 15;          // token group: {4tg..4tg+3, 64+4tg..+3}
    const int eg  = tid >> 4;          // expert group: 4eg..4eg+3 (eg 0..15)

    // acc[tp][e], f32x2 over token pairs; bias folded into init.
    unsigned long long acc[4][4];
#pragma unroll
    for (int e = 0; e < 4; e++) {
        const unsigned long long b2 = packdup(__ldg(&bg[4 * eg + e]));
#pragma unroll
        for (int tp = 0; tp < 4; tp++) acc[tp][e] = b2;
    }

    float4 la[2], lw;

#define LOAD(k0)                                                               \
    {                                                                          \
        _Pragma("unroll")                                                      \
        for (int i = 0; i < 2; i++) {                                          \
            const int j = tid + NTHREADS * i;                                  \
            const int m = j >> 2, q = j & 3;                                   \
            la[i] = *reinterpret_cast<const float4*>(                          \
                tokens + (size_t)(bm + m) * ND + (k0) + 4 * q);                \
        }                                                                      \
        {                                                                      \
            const int e = tid >> 2, q = tid & 3;                               \
            lw = *reinterpret_cast<const float4*>(                             \
                Wg + (size_t)e * ND + (k0) + 4 * q);                           \
        }                                                                      \
    }

// transpose scalar stores to padded rows (<=2-way bank conflicts)
#define STORE(buf)                                                             \
    {                                                                          \
        float* sa = smem + (buf) * A_STAGEF;                                   \
        float* sw = smem + W_BASE + (buf) * W_STAGEF;                          \
        _Pragma("unroll")                                                      \
        for (int i = 0; i < 2; i++) {                                          \
            const int j = tid + NTHREADS * i;                                  \
            const int m = j >> 2, q = j & 3;                                   \
            const float v[4] = {la[i].x, la[i].y, la[i].z, la[i].w};           \
            _Pragma("unroll")                                                  \
            for (int r = 0; r < 4; r++)                                        \
                sa[(4 * q + r) * ROWA + m] = v[r];                             \
        }                                                                      \
        {                                                                      \
            const int e = tid >> 2, q = tid & 3;                               \
            const float v[4] = {lw.x, lw.y, lw.z, lw.w};                       \
            _Pragma("unroll")                                                  \
            for (int r = 0; r < 4; r++)                                        \
                sw[(4 * q + r) * ROWW + e] = v[r];                             \
        }                                                                      \
    }

    LOAD(0);
    STORE(0);
    __syncthreads();

    const float* saT = smem + 4 * tg;            // + buf*A_STAGEF + k*ROWA
    const float* swT = smem + W_BASE + 4 * eg;   // + buf*W_STAGEF + k*ROWW

    for (int ch = 0; ch < NCHUNK; ch++) {
        const int buf = ch & 1;
        if (ch + 1 < NCHUNK) LOAD((ch + 1) * KC);

        const float* sa = saT + buf * A_STAGEF;
        const float* sw = swT + buf * W_STAGEF;

        // ---- explicit 2-deep software pipeline over k ----
        ulonglong2 A0c = *reinterpret_cast<const ulonglong2*>(sa);
        ulonglong2 A1c = *reinterpret_cast<const ulonglong2*>(sa + 64);
        float4     w0c = *reinterpret_cast<const float4*>(sw);

#pragma unroll
        for (int k = 0; k < KC; k++) {
            ulonglong2 A0n, A1n;
            float4 w0n;
            if (k + 1 < KC) {
                A0n = *reinterpret_cast<const ulonglong2*>(sa + (k + 1) * ROWA);
                A1n = *reinterpret_cast<const ulonglong2*>(sa + (k + 1) * ROWA + 64);
                w0n = *reinterpret_cast<const float4*>(sw + (k + 1) * ROWW);
            }

            const unsigned long long a64[4] = {A0c.x, A0c.y, A1c.x, A1c.y};
            const unsigned long long wd[4] = {
                packdup(w0c.x), packdup(w0c.y), packdup(w0c.z), packdup(w0c.w)};
#pragma unroll
            for (int tp = 0; tp < 4; tp++)
#pragma unroll
                for (int e = 0; e < 4; e++) fma2(acc[tp][e], a64[tp], wd[e]);

            if (k + 1 < KC) { A0c = A0n; A1c = A1n; w0c = w0n; }
        }

        if (ch + 1 < NCHUNK) STORE(buf ^ 1);   // disjoint buffer: safe pre-sync
        __syncthreads();
    }

    // ---- scatter acc -> swizzled logits overlay ----
    float* slog = smem;   // [128][64], col e ^ (m&31)
#pragma unroll
    for (int tp = 0; tp < 4; tp++) {
        const int m0 = ((tp & 1) ? 4 * tg + 2 : 4 * tg) + ((tp & 2) ? 64 : 0);
        const int m1 = m0 + 1;
#pragma unroll
        for (int e = 0; e < 4; e++) {
            const int ex = 4 * eg + e;
            slog[m0 * 64 + (ex ^ (m0 & 31))] =
                __uint_as_float((uint32_t)acc[tp][e]);
            slog[m1 * 64 + (ex ^ (m1 & 31))] =
                __uint_as_float((uint32_t)(acc[tp][e] >> 32));
        }
    }
    __syncthreads();

    // ---- per-token epilogue (identical math to the passing kernels;
    //      bias already inside the logits) ----
    if (tid < TILE_M) {
        const int m = tid;
        const int gtok = bm + m;
        const float cap = 0.5f + 1.1f * ((float)t_arr[gtok >> 12] / 1000.0f);
        const int msw = m & 31;
        const float* row = slog + m * 64;

        float p[NE];
#pragma unroll
        for (int e = 0; e < NE; e++) p[e] = row[e ^ msw];

        float mx = -3.402823466e38f;
#pragma unroll 8
        for (int e = 0; e < NE; e++) mx = fmaxf(mx, p[e]);
        float s = 0.0f;
#pragma unroll 4
        for (int e = 0; e < NE; e++) { const float v = expf(p[e] - mx); s += v; p[e] = v; }
        const float inv = 1.0f / s;

        float summin = 0.0f, sumex = 0.0f;
#pragma unroll 8
        for (int e = 0; e < NE; e++) {
            const float q = 0.85f * (p[e] * inv) + (0.15f / 64.0f);
            p[e] = q;
            const float cc = fminf(q, cap);
            summin += cc;
            sumex += q - cc;
        }
        const float hs = fmaxf(64.0f * cap - summin, 1e-8f);
        const float scale = sumex / hs;

        float v1 = -1.0f, v2 = -1.0f;
        int i1 = 0, i2 = 0;
#pragma unroll 8
        for (int e = 0; e < NE; e++) {
            const float cc = fminf(p[e], cap);
            const float f = cc + scale * (cap - cc);
            if (f > v1)      { v2 = v1; i2 = i1; v1 = f; i1 = e; }
            else if (f > v2) { v2 = f; i2 = e; }
        }

        float* orow = out + (size_t)gtok * NE;
        const float4 z = make_float4(0.f, 0.f, 0.f, 0.f);
#pragma unroll
        for (int u = 0; u < 16; u++) reinterpret_cast<float4*>(orow)[u] = z;
        orow[i1] = v1;
        orow[i2] = v2;
    }
}

extern "C" void kernel_launch(void* const* d_in, const int* in_sizes, int n_in,
                              void* d_out, int out_size)
{
    const float* tokens = (const float*)d_in[0];   // (16, 4096, 1024) f32
    const int*   t_arr  = (const int*)d_in[1];     // (16,) i32
    const float* Wg     = (const float*)d_in[2];   // (64, 1024) f32
    const float* bg     = (const float*)d_in[3];   // (64,) f32
    float*       out    = (float*)d_out;           // (16, 4096, 64) f32

    router_ffma2_kernel<<<NTOK / TILE_M, NTHREADS>>>(tokens, t_arr, Wg, bg, out);
}

// round 14
// speedup vs baseline: 1.0557x; 1.0557x over previous
#include <cuda_runtime.h>
#include <cstdint>

#define NE       64
#define ND       1024
#define NTOK     65536
#define TILE_M   128
#define KC       16              // fp32 K per pipeline stage
#define NCHUNK   (ND / KC)       // 64
#define NTHREADS 128

// ---- static smem layout (float indices), padded-linear ----
// A stage: [2][KC][132]  (128 tokens + 4 pad)
// W stage: [2][KC][132]  (64 experts duplicated -> 128 floats + 4 pad)
// epilogue overlay slog[128][64] = 8192 floats fits inside.
#define ROWA        132
#define A_STAGEF    (KC * ROWA)            // 2112
#define W_BASE      (2 * A_STAGEF)         // 4224
#define W_ROWF      132
#define W_STAGEF    (KC * W_ROWF)          // 2112
#define SMEM_FLOATS (W_BASE + 2 * W_STAGEF)  // 8448 floats = 33.8 KB

// W transposed + duplicated: g_Wt[k][128], Wt[k][2e] = Wt[k][2e+1] = W[e][k]
__device__ float g_Wt[ND * 2 * NE];

__device__ __forceinline__ void fma2(unsigned long long& acc,
                                     unsigned long long a,
                                     unsigned long long b) {
    asm("fma.rn.f32x2 %0, %1, %2, %0;" : "+l"(acc) : "l"(a), "l"(b));
}
__device__ __forceinline__ unsigned long long packdup(float f) {
    unsigned long long d;
    const uint32_t u = __float_as_uint(f);
    asm("mov.b64 %0, {%1, %1};" : "=l"(d) : "r"(u));
    return d;
}
__device__ __forceinline__ void cp16(uint32_t smem_dst, const void* gsrc) {
    asm volatile("cp.async.ca.shared.global [%0], [%1], 16;"
                 :: "r"(smem_dst), "l"(gsrc));
}
__device__ __forceinline__ void cp_commit() {
    asm volatile("cp.async.commit_group;" ::: "memory");
}
__device__ __forceinline__ void cp_wait0() {
    asm volatile("cp.async.wait_group 0;" ::: "memory");
}

// ---- prologue: W[e][k] -> g_Wt[k][2e]=[2e+1]  (runs once per launch) ----
__global__ __launch_bounds__(256)
void transpose_w_kernel(const float* __restrict__ Wg)
{
    const int idx = blockIdx.x * 256 + threadIdx.x;   // 0..65535 = k*64+e
    const int k = idx >> 6;
    const int e = idx & 63;
    const float v = Wg[(size_t)e * ND + k];
    g_Wt[k * 128 + 2 * e]     = v;
    g_Wt[k * 128 + 2 * e + 1] = v;
}

// =======================================================================
__global__ __launch_bounds__(NTHREADS, 4)
void router_ffma2_kernel(const float* __restrict__ tokens,
                         const int* __restrict__ t_arr,
                         const float* __restrict__ bg,
                         float* __restrict__ out)
{
    __shared__ __align__(16) float smem[SMEM_FLOATS];

    const int tid = threadIdx.x;
    const int bm  = blockIdx.x * TILE_M;
    const int tg  = tid & 15;          // token group: {4tg..4tg+3, 64+4tg..+3}
    const int eg  = tid >> 4;          // expert group: 8eg..8eg+7

    const uint32_t swbase =
        (uint32_t)__cvta_generic_to_shared(smem + W_BASE);

    // acc[tp][e], f32x2 over token pairs; bias folded into init.
    unsigned long long acc[4][8];
#pragma unroll
    for (int e = 0; e < 8; e++) {
        const unsigned long long b2 = packdup(__ldg(&bg[8 * eg + e]));
#pragma unroll
        for (int tp = 0; tp < 4; tp++) acc[tp][e] = b2;
    }

    float4 la[4];

#define LOAD_A(k0)                                                             \
    {                                                                          \
        _Pragma("unroll")                                                      \
        for (int i = 0; i < 4; i++) {                                          \
            const int j = tid + NTHREADS * i;                                  \
            const int m = j >> 2, q = j & 3;                                   \
            la[i] = *reinterpret_cast<const float4*>(                          \
                tokens + (size_t)(bm + m) * ND + (k0) + 4 * q);                \
        }                                                                      \
    }

// A transpose scalar stores to padded rows (<=2-way bank conflicts)
#define STORE_A(buf)                                                           \
    {                                                                          \
        float* sa = smem + (buf) * A_STAGEF;                                   \
        _Pragma("unroll")                                                      \
        for (int i = 0; i < 4; i++) {                                          \
            const int j = tid + NTHREADS * i;                                  \
            const int m = j >> 2, q = j & 3;                                   \
            const float v[4] = {la[i].x, la[i].y, la[i].z, la[i].w};           \
            _Pragma("unroll")                                                  \
            for (int r = 0; r < 4; r++)                                        \
                sa[(4 * q + r) * ROWA + m] = v[r];                             \
        }                                                                      \
    }

// W staging: straight cp.async copy of 16 dup rows (512B each) per chunk
#define WCOPY(buf, k0)                                                         \
    {                                                                          \
        const uint32_t base = swbase + (uint32_t)(buf) * (W_STAGEF * 4);       \
        _Pragma("unroll")                                                      \
        for (int i = 0; i < 4; i++) {                                          \
            const int o = tid + NTHREADS * i;                                  \
            const int kk = o >> 5, q = o & 31;                                 \
            cp16(base + (uint32_t)(kk * (W_ROWF * 4) + q * 16),                \
                 g_Wt + (size_t)((k0) + kk) * 128 + q * 4);                    \
        }                                                                      \
    }

    LOAD_A(0);
    WCOPY(0, 0);
    cp_commit();
    STORE_A(0);
    cp_wait0();
    __syncthreads();

    const float* saT = smem + 4 * tg;                     // + buf*A_STAGEF + k*ROWA
    const float* swT = smem + W_BASE + 16 * eg;           // + buf*W_STAGEF + k*W_ROWF

    for (int ch = 0; ch < NCHUNK; ch++) {
        const int buf = ch & 1;
        if (ch + 1 < NCHUNK) {
            LOAD_A((ch + 1) * KC);
            WCOPY(buf ^ 1, (ch + 1) * KC);
            cp_commit();
        }

        const float* sa = saT + buf * A_STAGEF;
        const float* sw = swT + buf * W_STAGEF;

        // ---- 2-deep A pipeline over k; W dup-pairs loaded per k (no packdup) ----
        ulonglong2 A0c = *reinterpret_cast<const ulonglong2*>(sa);
        ulonglong2 A1c = *reinterpret_cast<const ulonglong2*>(sa + 64);

#pragma unroll
        for (int k = 0; k < KC; k++) {
            ulonglong2 A0n, A1n;
            if (k + 1 < KC) {
                A0n = *reinterpret_cast<const ulonglong2*>(sa + (k + 1) * ROWA);
                A1n = *reinterpret_cast<const ulonglong2*>(sa + (k + 1) * ROWA + 64);
            }

            const ulonglong2 W0 =
                *reinterpret_cast<const ulonglong2*>(sw + k * W_ROWF);
            const ulonglong2 W1 =
                *reinterpret_cast<const ulonglong2*>(sw + k * W_ROWF + 4);
            const ulonglong2 W2 =
                *reinterpret_cast<const ulonglong2*>(sw + k * W_ROWF + 8);
            const ulonglong2 W3 =
                *reinterpret_cast<const ulonglong2*>(sw + k * W_ROWF + 12);

            const unsigned long long a64[4] = {A0c.x, A0c.y, A1c.x, A1c.y};
            const unsigned long long wd[8] = {W0.x, W0.y, W1.x, W1.y,
                                              W2.x, W2.y, W3.x, W3.y};
#pragma unroll
            for (int tp = 0; tp < 4; tp++)
#pragma unroll
                for (int e = 0; e < 8; e++) fma2(acc[tp][e], a64[tp], wd[e]);

            if (k + 1 < KC) { A0c = A0n; A1c = A1n; }
        }

        if (ch + 1 < NCHUNK) {
            STORE_A(buf ^ 1);   // disjoint buffer: safe pre-sync
            cp_wait0();         // next chunk's W landed
        }
        __syncthreads();
    }

    // ---- scatter acc -> swizzled logits overlay ----
    float* slog = smem;   // [128][64], col e ^ (m&31)
#pragma unroll
    for (int tp = 0; tp < 4; tp++) {
        const int m0 = ((tp & 1) ? 4 * tg + 2 : 4 * tg) + ((tp & 2) ? 64 : 0);
        const int m1 = m0 + 1;
#pragma unroll
        for (int e = 0; e < 8; e++) {
            const int ex = 8 * eg + e;
            slog[m0 * 64 + (ex ^ (m0 & 31))] =
                __uint_as_float((uint32_t)acc[tp][e]);
            slog[m1 * 64 + (ex ^ (m1 & 31))] =
                __uint_as_float((uint32_t)(acc[tp][e] >> 32));
        }
    }
    __syncthreads();

    // ---- per-token epilogue (identical math to the passing kernels;
    //      bias already inside the logits) ----
    {
        const int m = tid;
        const int gtok = bm + m;
        const float cap = 0.5f + 1.1f * ((float)t_arr[gtok >> 12] / 1000.0f);
        const int msw = m & 31;
        const float* row = slog + m * 64;

        float p[NE];
#pragma unroll
        for (int e = 0; e < NE; e++) p[e] = row[e ^ msw];

        float mx = -3.402823466e38f;
#pragma unroll 8
        for (int e = 0; e < NE; e++) mx = fmaxf(mx, p[e]);
        float s = 0.0f;
#pragma unroll 4
        for (int e = 0; e < NE; e++) { const float v = expf(p[e] - mx); s += v; p[e] = v; }
        const float inv = 1.0f / s;

        float summin = 0.0f, sumex = 0.0f;
#pragma unroll 8
        for (int e = 0; e < NE; e++) {
            const float q = 0.85f * (p[e] * inv) + (0.15f / 64.0f);
            p[e] = q;
            const float cc = fminf(q, cap);
            summin += cc;
            sumex += q - cc;
        }
        const float hs = fmaxf(64.0f * cap - summin, 1e-8f);
        const float scale = sumex / hs;

        float v1 = -1.0f, v2 = -1.0f;
        int i1 = 0, i2 = 0;
#pragma unroll 8
        for (int e = 0; e < NE; e++) {
            const float cc = fminf(p[e], cap);
            const float f = cc + scale * (cap - cc);
            if (f > v1)      { v2 = v1; i2 = i1; v1 = f; i1 = e; }
            else if (f > v2) { v2 = f; i2 = e; }
        }

        float* orow = out + (size_t)gtok * NE;
        const float4 z = make_float4(0.f, 0.f, 0.f, 0.f);
#pragma unroll
        for (int u = 0; u < 16; u++) reinterpret_cast<float4*>(orow)[u] = z;
        orow[i1] = v1;
        orow[i2] = v2;
    }
}

extern "C" void kernel_launch(void* const* d_in, const int* in_sizes, int n_in,
                              void* d_out, int out_size)
{
    const float* tokens = (const float*)d_in[0];   // (16, 4096, 1024) f32
    const int*   t_arr  = (const int*)d_in[1];     // (16,) i32
    const float* Wg     = (const float*)d_in[2];   // (64, 1024) f32
    const float* bg     = (const float*)d_in[3];   // (64,) f32
    float*       out    = (float*)d_out;           // (16, 4096, 64) f32

    transpose_w_kernel<<<256, 256>>>(Wg);
    router_ffma2_kernel<<<NTOK / TILE_M, NTHREADS>>>(tokens, t_arr, bg, out);
}

// round 15
// speedup vs baseline: 1.1396x; 1.0795x over previous
#include <cuda_runtime.h>
#include <cstdint>

#define NE       64
#define ND       1024
#define NTOK     65536
#define TILE_M   128
#define KC       32              // fp32 K per pipeline stage (doubled)
#define KH       16              // staging half-chunk
#define NCHUNK   (ND / KC)       // 32
#define NTHREADS 128

// ---- dynamic smem layout (float indices), padded-linear ----
// A stage: [2][KC][132]  (128 tokens + 4 pad)
// W stage: [2][KC][68]   (64 experts + 4 pad)
// epilogue overlay slog[128][64] = 8192 floats fits inside.
#define ROWA        132
#define ROWW        68
#define A_STAGEF    (KC * ROWA)            // 4224
#define W_BASE      (2 * A_STAGEF)         // 8448
#define W_STAGEF    (KC * ROWW)            // 2176
#define SMEM_FLOATS (W_BASE + 2 * W_STAGEF)  // 12800 floats = 51200 B

__device__ __forceinline__ void fma2(unsigned long long& acc,
                                     unsigned long long a,
                                     unsigned long long b) {
    asm("fma.rn.f32x2 %0, %1, %2, %0;" : "+l"(acc) : "l"(a), "l"(b));
}
__device__ __forceinline__ unsigned long long packdup(float f) {
    unsigned long long d;
    const uint32_t u = __float_as_uint(f);
    asm("mov.b64 %0, {%1, %1};" : "=l"(d) : "r"(u));
    return d;
}

__global__ __launch_bounds__(NTHREADS, 4)
void router_ffma2_kernel(const float* __restrict__ tokens,
                         const int* __restrict__ t_arr,
                         const float* __restrict__ Wg,
                         const float* __restrict__ bg,
                         float* __restrict__ out)
{
    extern __shared__ __align__(16) float smem[];

    const int tid = threadIdx.x;
    const int bm  = blockIdx.x * TILE_M;
    const int tg  = tid & 15;          // token group: {4tg..4tg+3, 64+4tg..+3}
    const int eg  = tid >> 4;          // expert group: 8eg..8eg+7

    // acc[tp][e], f32x2 over token pairs; bias folded into init.
    unsigned long long acc[4][8];
#pragma unroll
    for (int e = 0; e < 8; e++) {
        const unsigned long long b2 = packdup(__ldg(&bg[8 * eg + e]));
#pragma unroll
        for (int tp = 0; tp < 4; tp++) acc[tp][e] = b2;
    }

    float4 la[4], lw[2];

// loads one 16-wide k half starting at global k0 (same shape as r11 LOAD)
#define LOAD_H(k0)                                                             \
    {                                                                          \
        _Pragma("unroll")                                                      \
        for (int i = 0; i < 4; i++) {                                          \
            const int j = tid + NTHREADS * i;                                  \
            const int m = j >> 2, q = j & 3;                                   \
            la[i] = *reinterpret_cast<const float4*>(                          \
                tokens + (size_t)(bm + m) * ND + (k0) + 4 * q);                \
        }                                                                      \
        _Pragma("unroll")                                                      \
        for (int i = 0; i < 2; i++) {                                          \
            const int j = tid + NTHREADS * i;                                  \
            const int e = j >> 2, q = j & 3;                                   \
            lw[i] = *reinterpret_cast<const float4*>(                          \
                Wg + (size_t)e * ND + (k0) + 4 * q);                           \
        }                                                                      \
    }

// stores the held half into stage `buf`, k-rows kb..kb+15 (<=2-way conflicts)
#define STORE_H(buf, kb)                                                       \
    {                                                                          \
        float* sa = smem + (buf) * A_STAGEF + (kb) * ROWA;                     \
        float* sw = smem + W_BASE + (buf) * W_STAGEF + (kb) * ROWW;            \
        _Pragma("unroll")                                                      \
        for (int i = 0; i < 4; i++) {                                          \
            const int j = tid + NTHREADS * i;                                  \
            const int m = j >> 2, q = j & 3;                                   \
            const float v[4] = {la[i].x, la[i].y, la[i].z, la[i].w};           \
            _Pragma("unroll")                                                  \
            for (int r = 0; r < 4; r++)                                        \
                sa[(4 * q + r) * ROWA + m] = v[r];                             \
        }                                                                      \
        _Pragma("unroll")                                                      \
        for (int i = 0; i < 2; i++) {                                          \
            const int j = tid + NTHREADS * i;                                  \
            const int e = j >> 2, q = j & 3;                                   \
            const float v[4] = {lw[i].x, lw[i].y, lw[i].z, lw[i].w};           \
            _Pragma("unroll")                                                  \
            for (int r = 0; r < 4; r++)                                        \
                sw[(4 * q + r) * ROWW + e] = v[r];                             \
        }                                                                      \
    }

// 16-k pipelined compute segment on stage `buf` starting at k-row kb
#define COMPUTE16(buf, kb)                                                     \
    {                                                                          \
        const float* sa = saT + (buf) * A_STAGEF + (kb) * ROWA;                \
        const float* sw = swT + (buf) * W_STAGEF + (kb) * ROWW;                \
        ulonglong2 A0c = *reinterpret_cast<const ulonglong2*>(sa);             \
        ulonglong2 A1c = *reinterpret_cast<const ulonglong2*>(sa + 64);        \
        float4     w0c = *reinterpret_cast<const float4*>(sw);                 \
        float4     w1c = *reinterpret_cast<const float4*>(sw + 4);             \
        _Pragma("unroll")                                                      \
        for (int k = 0; k < KH; k++) {                                         \
            ulonglong2 A0n, A1n;                                               \
            float4 w0n, w1n;                                                   \
            if (k + 1 < KH) {                                                  \
                A0n = *reinterpret_cast<const ulonglong2*>(                    \
                    sa + (k + 1) * ROWA);                                      \
                A1n = *reinterpret_cast<const ulonglong2*>(                    \
                    sa + (k + 1) * ROWA + 64);                                 \
                w0n = *reinterpret_cast<const float4*>(sw + (k + 1) * ROWW);   \
                w1n = *reinterpret_cast<const float4*>(                        \
                    sw + (k + 1) * ROWW + 4);                                  \
            }                                                                  \
            const unsigned long long a64[4] = {A0c.x, A0c.y, A1c.x, A1c.y};    \
            const unsigned long long wd[8] = {                                 \
                packdup(w0c.x), packdup(w0c.y), packdup(w0c.z),                \
                packdup(w0c.w), packdup(w1c.x), packdup(w1c.y),                \
                packdup(w1c.z), packdup(w1c.w)};                               \
            _Pragma("unroll")                                                  \
            for (int tp = 0; tp < 4; tp++)                                     \
                _Pragma("unroll")                                              \
                for (int e = 0; e < 8; e++) fma2(acc[tp][e], a64[tp], wd[e]);  \
            if (k + 1 < KH) { A0c = A0n; A1c = A1n; w0c = w0n; w1c = w1n; }    \
        }                                                                      \
    }

    // prologue: stage chunk 0 (both halves)
    LOAD_H(0);
    STORE_H(0, 0);
    LOAD_H(KH);
    STORE_H(0, KH);
    __syncthreads();

    const float* saT = smem + 4 * tg;            // + buf*A_STAGEF + k*ROWA
    const float* swT = smem + W_BASE + 8 * eg;   // + buf*W_STAGEF + k*ROWW

    for (int ch = 0; ch < NCHUNK; ch++) {
        const int buf = ch & 1;
        const bool more = (ch + 1 < NCHUNK);

        if (more) LOAD_H((ch + 1) * KC);          // next chunk, half 0

        COMPUTE16(buf, 0);                        // k 0..15 of this chunk

        if (more) {
            STORE_H(buf ^ 1, 0);                  // disjoint buffer, safe
            LOAD_H((ch + 1) * KC + KH);           // next chunk, half 1
        }

        COMPUTE16(buf, KH);                       // k 16..31 of this chunk

        if (more) STORE_H(buf ^ 1, KH);
        __syncthreads();
    }

    // ---- scatter acc -> swizzled logits overlay ----
    float* slog = smem;   // [128][64], col e ^ (m&31)
#pragma unroll
    for (int tp = 0; tp < 4; tp++) {
        const int m0 = ((tp & 1) ? 4 * tg + 2 : 4 * tg) + ((tp & 2) ? 64 : 0);
        const int m1 = m0 + 1;
#pragma unroll
        for (int e = 0; e < 8; e++) {
            const int ex = 8 * eg + e;
            slog[m0 * 64 + (ex ^ (m0 & 31))] =
                __uint_as_float((uint32_t)acc[tp][e]);
            slog[m1 * 64 + (ex ^ (m1 & 31))] =
                __uint_as_float((uint32_t)(acc[tp][e] >> 32));
        }
    }
    __syncthreads();

    // ---- per-token epilogue (identical math to the passing kernels;
    //      bias already inside the logits) ----
    {
        const int m = tid;
        const int gtok = bm + m;
        const float cap = 0.5f + 1.1f * ((float)t_arr[gtok >> 12] / 1000.0f);
        const int msw = m & 31;
        const float* row = slog + m * 64;

        float p[NE];
#pragma unroll
        for (int e = 0; e < NE; e++) p[e] = row[e ^ msw];

        float mx = -3.402823466e38f;
#pragma unroll 8
        for (int e = 0; e < NE; e++) mx = fmaxf(mx, p[e]);
        float s = 0.0f;
#pragma unroll 4
        for (int e = 0; e < NE; e++) { const float v = expf(p[e] - mx); s += v; p[e] = v; }
        const float inv = 1.0f / s;

        float summin = 0.0f, sumex = 0.0f;
#pragma unroll 8
        for (int e = 0; e < NE; e++) {
            const float q = 0.85f * (p[e] * inv) + (0.15f / 64.0f);
            p[e] = q;
            const float cc = fminf(q, cap);
            summin += cc;
            sumex += q - cc;
        }
        const float hs = fmaxf(64.0f * cap - summin, 1e-8f);
        const float scale = sumex / hs;

        float v1 = -1.0f, v2 = -1.0f;
        int i1 = 0, i2 = 0;
#pragma unroll 8
        for (int e = 0; e < NE; e++) {
            const float cc = fminf(p[e], cap);
            const float f = cc + scale * (cap - cc);
            if (f > v1)      { v2 = v1; i2 = i1; v1 = f; i1 = e; }
            else if (f > v2) { v2 = f; i2 = e; }
        }

        float* orow = out + (size_t)gtok * NE;
        const float4 z = make_float4(0.f, 0.f, 0.f, 0.f);
#pragma unroll
        for (int u = 0; u < 16; u++) reinterpret_cast<float4*>(orow)[u] = z;
        orow[i1] = v1;
        orow[i2] = v2;
    }
}

extern "C" void kernel_launch(void* const* d_in, const int* in_sizes, int n_in,
                              void* d_out, int out_size)
{
    const float* tokens = (const float*)d_in[0];   // (16, 4096, 1024) f32
    const int*   t_arr  = (const int*)d_in[1];     // (16,) i32
    const float* Wg     = (const float*)d_in[2];   // (64, 1024) f32
    const float* bg     = (const float*)d_in[3];   // (64,) f32
    float*       out    = (float*)d_out;           // (16, 4096, 64) f32

    cudaFuncSetAttribute(router_ffma2_kernel,
                         cudaFuncAttributeMaxDynamicSharedMemorySize,
                         SMEM_FLOATS * 4);

    router_ffma2_kernel<<<NTOK / TILE_M, NTHREADS, SMEM_FLOATS * 4>>>(
        tokens, t_arr, Wg, bg, out);
}

// round 16
// speedup vs baseline: 1.2201x; 1.0706x over previous
#include <cuda_runtime.h>
#include <cstdint>

#define NE       64
#define ND       1024
#define NTOK     65536
#define TILE_M   128
#define KC       32
#define KH       16
#define NCHUNK   (ND / KC)       // 32
#define NTHREADS 160             // 4 consumer warps + 1 producer warp

// ---- dynamic smem layout (float indices), padded-linear ----
#define ROWA        132
#define ROWW        68
#define A_STAGEF    (KC * ROWA)              // 4224
#define W_BASE      (2 * A_STAGEF)           // 8448
#define W_STAGEF    (KC * ROWW)              // 2176
#define SMEM_FLOATS (W_BASE + 2 * W_STAGEF)  // 12800 floats = 51200 B

// named barriers: FULL per (buf, warp) ids 1..8 cnt 64; EMPTY per buf ids 9..10 cnt 160
#define BAR_SYNC(id, cnt)                                                      \
    asm volatile("bar.sync %0, %1;" :: "r"(id), "r"(cnt) : "memory")
#define BAR_ARRIVE(id, cnt)                                                    \
    asm volatile("bar.arrive %0, %1;" :: "r"(id), "r"(cnt) : "memory")
#define FULLB(buf, w) (1 + (buf) * 4 + (w))
#define EMPTYB(buf)   (9 + (buf))
#define JOIN1 11
#define JOIN2 12

__device__ __forceinline__ void fma2(unsigned long long& acc,
                                     unsigned long long a,
                                     unsigned long long b) {
    asm("fma.rn.f32x2 %0, %1, %2, %0;" : "+l"(acc) : "l"(a), "l"(b));
}
__device__ __forceinline__ unsigned long long packdup(float f) {
    unsigned long long d;
    const uint32_t u = __float_as_uint(f);
    asm("mov.b64 %0, {%1, %1};" : "=l"(d) : "r"(u));
    return d;
}

__global__ __launch_bounds__(NTHREADS, 3)
void router_ffma2_kernel(const float* __restrict__ tokens,
                         const int* __restrict__ t_arr,
                         const float* __restrict__ Wg,
                         const float* __restrict__ bg,
                         float* __restrict__ out)
{
    extern __shared__ __align__(16) float smem[];

    const int tid = threadIdx.x;
    const int wid = tid >> 5;
    const int bm  = blockIdx.x * TILE_M;

    if (wid == 4) {
        // ======================= producer warp =======================
        const int lane = tid & 31;
        float4 pa[4][4], pw[4][2];

        for (int ch = 0; ch < NCHUNK; ch++) {
            const int buf = ch & 1;
            if (ch >= 2) BAR_SYNC(EMPTYB(buf), 160);
            const int k0 = ch * KC;

#pragma unroll
            for (int h = 0; h < 2; h++) {
                const int kh = k0 + h * KH;
                // ---- load one 16-k half (24 LDG.128 in flight) ----
#pragma unroll
                for (int rr = 0; rr < 4; rr++) {
#pragma unroll
                    for (int i = 0; i < 4; i++) {
                        const int j = (lane + 32 * rr) + 128 * i;
                        const int m = j >> 2, q = j & 3;
                        pa[rr][i] = *reinterpret_cast<const float4*>(
                            tokens + (size_t)(bm + m) * ND + kh + 4 * q);
                    }
#pragma unroll
                    for (int i = 0; i < 2; i++) {
                        const int j = (lane + 32 * rr) + 128 * i;
                        const int e = j >> 2, q = j & 3;
                        pw[rr][i] = *reinterpret_cast<const float4*>(
                            Wg + (size_t)e * ND + kh + 4 * q);
                    }
                }
                // ---- transpose-store the half ----
                float* sa = smem + buf * A_STAGEF + h * KH * ROWA;
                float* sw = smem + W_BASE + buf * W_STAGEF + h * KH * ROWW;
#pragma unroll
                for (int rr = 0; rr < 4; rr++) {
#pragma unroll
                    for (int i = 0; i < 4; i++) {
                        const int j = (lane + 32 * rr) + 128 * i;
                        const int m = j >> 2, q = j & 3;
                        const float v[4] = {pa[rr][i].x, pa[rr][i].y,
                                            pa[rr][i].z, pa[rr][i].w};
#pragma unroll
                        for (int r = 0; r < 4; r++)
                            sa[(4 * q + r) * ROWA + m] = v[r];
                    }
#pragma unroll
                    for (int i = 0; i < 2; i++) {
                        const int j = (lane + 32 * rr) + 128 * i;
                        const int e = j >> 2, q = j & 3;
                        const float v[4] = {pw[rr][i].x, pw[rr][i].y,
                                            pw[rr][i].z, pw[rr][i].w};
#pragma unroll
                        for (int r = 0; r < 4; r++)
                            sw[(4 * q + r) * ROWW + e] = v[r];
                    }
                }
            }
            __threadfence_block();
            BAR_ARRIVE(FULLB(buf, 0), 64);
            BAR_ARRIVE(FULLB(buf, 1), 64);
            BAR_ARRIVE(FULLB(buf, 2), 64);
            BAR_ARRIVE(FULLB(buf, 3), 64);
        }
        BAR_SYNC(JOIN1, 160);   // consumers may scatter into the overlay
        BAR_SYNC(JOIN2, 160);   // consumers run the epilogue
    } else {
        // ======================= consumer warps =======================
        const int tg = tid & 15;          // tokens {4tg..4tg+3, 64+4tg..+3}
        const int eg = tid >> 4;          // experts 8eg..8eg+7 (0..7)

        unsigned long long acc[4][8];
#pragma unroll
        for (int e = 0; e < 8; e++) {
            const unsigned long long b2 = packdup(__ldg(&bg[8 * eg + e]));
#pragma unroll
            for (int tp = 0; tp < 4; tp++) acc[tp][e] = b2;
        }

        const float* saT = smem + 4 * tg;
        const float* swT = smem + W_BASE + 8 * eg;

#define COMPUTE16(buf, kb)                                                     \
    {                                                                          \
        const float* sa = saT + (buf) * A_STAGEF + (kb) * ROWA;                \
        const float* sw = swT + (buf) * W_STAGEF + (kb) * ROWW;                \
        ulonglong2 A0c = *reinterpret_cast<const ulonglong2*>(sa);             \
        ulonglong2 A1c = *reinterpret_cast<const ulonglong2*>(sa + 64);        \
        float4     w0c = *reinterpret_cast<const float4*>(sw);                 \
        float4     w1c = *reinterpret_cast<const float4*>(sw + 4);             \
        _Pragma("unroll")                                                      \
        for (int k = 0; k < KH; k++) {                                         \
            ulonglong2 A0n, A1n;                                               \
            float4 w0n, w1n;                                                   \
            if (k + 1 < KH) {                                                  \
                A0n = *reinterpret_cast<const ulonglong2*>(                    \
                    sa + (k + 1) * ROWA);                                      \
                A1n = *reinterpret_cast<const ulonglong2*>(                    \
                    sa + (k + 1) * ROWA + 64);                                 \
                w0n = *reinterpret_cast<const float4*>(sw + (k + 1) * ROWW);   \
                w1n = *reinterpret_cast<const float4*>(                        \
                    sw + (k + 1) * ROWW + 4);                                  \
            }                                                                  \
            const unsigned long long a64[4] = {A0c.x, A0c.y, A1c.x, A1c.y};    \
            const unsigned long long wd[8] = {                                 \
                packdup(w0c.x), packdup(w0c.y), packdup(w0c.z),                \
                packdup(w0c.w), packdup(w1c.x), packdup(w1c.y),                \
                packdup(w1c.z), packdup(w1c.w)};                               \
            _Pragma("unroll")                                                  \
            for (int tp = 0; tp < 4; tp++)                                     \
                _Pragma("unroll")                                              \
                for (int e = 0; e < 8; e++) fma2(acc[tp][e], a64[tp], wd[e]);  \
            if (k + 1 < KH) { A0c = A0n; A1c = A1n; w0c = w0n; w1c = w1n; }    \
        }                                                                      \
    }

        for (int ch = 0; ch < NCHUNK; ch++) {
            const int buf = ch & 1;
            BAR_SYNC(FULLB(buf, wid), 64);
            COMPUTE16(buf, 0);
            COMPUTE16(buf, KH);
            BAR_ARRIVE(EMPTYB(buf), 160);
        }

        BAR_SYNC(JOIN1, 160);   // all warps done reading stage buffers

        // ---- scatter acc -> swizzled logits overlay ----
        float* slog = smem;   // [128][64], col e ^ (m&31)
#pragma unroll
        for (int tp = 0; tp < 4; tp++) {
            const int m0 =
                ((tp & 1) ? 4 * tg + 2 : 4 * tg) + ((tp & 2) ? 64 : 0);
            const int m1 = m0 + 1;
#pragma unroll
            for (int e = 0; e < 8; e++) {
                const int ex = 8 * eg + e;
                slog[m0 * 64 + (ex ^ (m0 & 31))] =
                    __uint_as_float((uint32_t)acc[tp][e]);
                slog[m1 * 64 + (ex ^ (m1 & 31))] =
                    __uint_as_float((uint32_t)(acc[tp][e] >> 32));
            }
        }

        BAR_SYNC(JOIN2, 160);   // scatter visible to every consumer

        // ---- per-token epilogue (identical math to the passing kernels;
        //      bias already inside the logits) ----
        {
            const int m = tid;                 // 0..127 = token in tile
            const int gtok = bm + m;
            const float cap =
                0.5f + 1.1f * ((float)t_arr[gtok >> 12] / 1000.0f);
            const int msw = m & 31;
            const float* row = slog + m * 64;

            float p[NE];
#pragma unroll
            for (int e = 0; e < NE; e++) p[e] = row[e ^ msw];

            float mx = -3.402823466e38f;
#pragma unroll 8
            for (int e = 0; e < NE; e++) mx = fmaxf(mx, p[e]);
            float s = 0.0f;
#pragma unroll 4
            for (int e = 0; e < NE; e++) {
                const float v = expf(p[e] - mx);
                s += v;
                p[e] = v;
            }
            const float inv = 1.0f / s;

            float summin = 0.0f, sumex = 0.0f;
#pragma unroll 8
            for (int e = 0; e < NE; e++) {
                const float q = 0.85f * (p[e] * inv) + (0.15f / 64.0f);
                p[e] = q;
                const float cc = fminf(q, cap);
                summin += cc;
                sumex += q - cc;
            }
            const float hs = fmaxf(64.0f * cap - summin, 1e-8f);
            const float scale = sumex / hs;

            float v1 = -1.0f, v2 = -1.0f;
            int i1 = 0, i2 = 0;
#pragma unroll 8
            for (int e = 0; e < NE; e++) {
                const float cc = fminf(p[e], cap);
                const float f = cc + scale * (cap - cc);
                if (f > v1)      { v2 = v1; i2 = i1; v1 = f; i1 = e; }
                else if (f > v2) { v2 = f; i2 = e; }
            }

            float* orow = out + (size_t)gtok * NE;
            const float4 z = make_float4(0.f, 0.f, 0.f, 0.f);
#pragma unroll
            for (int u = 0; u < 16; u++)
                reinterpret_cast<float4*>(orow)[u] = z;
            orow[i1] = v1;
            orow[i2] = v2;
        }
    }
}

extern "C" void kernel_launch(void* const* d_in, const int* in_sizes, int n_in,
                              void* d_out, int out_size)
{
    const float* tokens = (const float*)d_in[0];   // (16, 4096, 1024) f32
    const int*   t_arr  = (const int*)d_in[1];     // (16,) i32
    const float* Wg     = (const float*)d_in[2];   // (64, 1024) f32
    const float* bg     = (const float*)d_in[3];   // (64,) f32
    float*       out    = (float*)d_out;           // (16, 4096, 64) f32

    cudaFuncSetAttribute(router_ffma2_kernel,
                         cudaFuncAttributeMaxDynamicSharedMemorySize,
                         SMEM_FLOATS * 4);

    router_ffma2_kernel<<<NTOK / TILE_M, NTHREADS, SMEM_FLOATS * 4>>>(
        tokens, t_arr, Wg, bg, out);
}